// round 13
// baseline (speedup 1.0000x reference)
#include <cuda_runtime.h>
#include <math.h>

// GlobalAttentionPooling, single pass, load-balanced, 2 kernels.
// Phase 1: 4736 warp-chunks of C contiguous nodes; each warp reads the sorted
//          segment ids for its chunk directly (ballot-based piece boundaries),
//          runs per-piece online softmax, flushes partials (m, sum, acc[256])
//          to collision-free scratch, and records segment extents (ss/es).
// Phase 2: one CTA per segment; two-pass merge (max, then independent
//          scaled accumulation) so all piece loads are in flight at once.

#define DD   256
#define MAXB 4096
#define NWC  4736          // total warp-chunks (1184 CTAs x 4 warps, one wave)
#define G1   1184

// segment extents, produced by phase1 (empty segments stay 0 -> es<=ss)
__device__ int g_ss[MAXB];
__device__ int g_es[MAXB];

// scratch partials
__device__ float g_cp_m[NWC];
__device__ float g_cp_s[NWC];
__device__ float g_cp_acc[NWC * DD];          // whole-chunk pieces
__device__ float g_sp_m[MAXB * 2];
__device__ float g_sp_s[MAXB * 2];
__device__ float g_sp_acc[MAXB * 2 * DD];     // head/tail partial pieces

// Read segment id at position p. stride=2 reads the low word of int64 ids.
__device__ __forceinline__ int loadSeg(const int* __restrict__ seg32, int stride, int p) {
    return __ldg(&seg32[(size_t)p * stride]);
}

__device__ __forceinline__ float dot8(const float4& a_lo, const float4& a_hi,
                                      const float4& w_lo, const float4& w_hi) {
    float g;
    g = a_lo.x * w_lo.x;
    g = fmaf(a_lo.y, w_lo.y, g);
    g = fmaf(a_lo.z, w_lo.z, g);
    g = fmaf(a_lo.w, w_lo.w, g);
    g = fmaf(a_hi.x, w_hi.x, g);
    g = fmaf(a_hi.y, w_hi.y, g);
    g = fmaf(a_hi.z, w_hi.z, g);
    g = fmaf(a_hi.w, w_hi.w, g);
    return g;
}

#define ACC_UPDATE(g, vlo, vhi)                                                   \
    do {                                                                          \
        if ((g) > m) {                                                            \
            const float r_ = __expf(m - (g));                                     \
            m = (g);                                                              \
            ssum = fmaf(ssum, r_, 1.0f);                                          \
            acc_lo.x = fmaf(acc_lo.x, r_, (vlo).x); acc_lo.y = fmaf(acc_lo.y, r_, (vlo).y); \
            acc_lo.z = fmaf(acc_lo.z, r_, (vlo).z); acc_lo.w = fmaf(acc_lo.w, r_, (vlo).w); \
            acc_hi.x = fmaf(acc_hi.x, r_, (vhi).x); acc_hi.y = fmaf(acc_hi.y, r_, (vhi).y); \
            acc_hi.z = fmaf(acc_hi.z, r_, (vhi).z); acc_hi.w = fmaf(acc_hi.w, r_, (vhi).w); \
        } else {                                                                  \
            const float e_ = __expf((g) - m);                                     \
            ssum += e_;                                                           \
            acc_lo.x = fmaf(e_, (vlo).x, acc_lo.x); acc_lo.y = fmaf(e_, (vlo).y, acc_lo.y); \
            acc_lo.z = fmaf(e_, (vlo).z, acc_lo.z); acc_lo.w = fmaf(e_, (vlo).w, acc_lo.w); \
            acc_hi.x = fmaf(e_, (vhi).x, acc_hi.x); acc_hi.y = fmaf(e_, (vhi).y, acc_hi.y); \
            acc_hi.z = fmaf(e_, (vhi).z, acc_hi.z); acc_hi.w = fmaf(e_, (vhi).w, acc_hi.w); \
        }                                                                         \
    } while (0)

__global__ __launch_bounds__(128, 8) void pool_phase1(
    const float* __restrict__ feat,
    const float* __restrict__ Wg,
    const int* __restrict__ seg32,
    int n, int C)
{
    const int lane = threadIdx.x & 31;
    const int warp = threadIdx.x >> 5;
    const int w    = blockIdx.x * 4 + warp;   // global warp-chunk id

    const int a = w * C;
    if (a >= n) return;
    const int b   = min(a + C, n);
    const int len = b - a;                    // <= 96

    // dtype detection: little-endian int64 (values < 2^31), n even -> int32
    // view at odd index n-1 is a high word = 0; sorted int32 last id != 0.
    const int stride = (__ldg(&seg32[n - 1]) == 0) ? 2 : 1;

    // ---- preload chunk ids + boundary ballots (all L2-resident) ----
    int      myid[3];
    unsigned bm[3];
    #pragma unroll
    for (int k = 0; k < 3; ++k) {
        const int pos = k * 32 + lane;        // relative to a
        const int idv = (pos < len) ? loadSeg(seg32, stride, a + pos) : 0x7fffffff;
        myid[k] = idv;
        const bool d = (pos > 0 && pos < len) &&
                       (idv != loadSeg(seg32, stride, a + pos - 1));
        bm[k] = __ballot_sync(0xffffffffu, d);
    }
    const int prevA = (a > 0) ? loadSeg(seg32, stride, a - 1) : -1;
    const int nextB = (b < n) ? loadSeg(seg32, stride, b) : -1;

    const float4* W4  = (const float4*)Wg;
    const float4 w_lo = W4[lane];
    const float4 w_hi = W4[lane + 32];

    int cur = a;
    while (cur < b) {
        const int rel = cur - a;

        // next boundary strictly after rel (uniform across warp)
        int pe_rel = len;
        #pragma unroll
        for (int k = 0; k < 3; ++k) {
            const int base = k * 32;
            unsigned mm = bm[k];
            const int sh = rel + 1 - base;
            if (sh > 0) mm = (sh >= 32) ? 0u : (mm & (0xffffffffu << sh));
            const int cand = mm ? (base + __ffs(mm) - 1) : len;
            pe_rel = min(pe_rel, cand);
        }
        const int pe = a + pe_rel;

        // segment id of this piece (uniform select + broadcast + safety clamp)
        const int k_    = rel >> 5;
        const int idsel = (k_ == 0) ? myid[0] : ((k_ == 1) ? myid[1] : myid[2]);
        int s = __shfl_sync(0xffffffffu, idsel, rel & 31);
        s = min(max(s, 0), MAXB - 1);          // guard scratch indexing

        // ---- online softmax over piece [cur, pe) ----
        float4 acc_lo = make_float4(0.f, 0.f, 0.f, 0.f);
        float4 acc_hi = make_float4(0.f, 0.f, 0.f, 0.f);
        float  m = -INFINITY, ssum = 0.0f;

        int i = cur;
        for (; i + 1 < pe; i += 2) {
            const float4* r0 = (const float4*)(feat + (size_t)i * DD);
            const float4* r1 = (const float4*)(feat + (size_t)(i + 1) * DD);
            const float4 v0_lo = __ldcs(&r0[lane]);
            const float4 v0_hi = __ldcs(&r0[lane + 32]);
            const float4 v1_lo = __ldcs(&r1[lane]);
            const float4 v1_hi = __ldcs(&r1[lane + 32]);

            float g0 = dot8(v0_lo, v0_hi, w_lo, w_hi);
            float g1 = dot8(v1_lo, v1_hi, w_lo, w_hi);
            #pragma unroll
            for (int off = 16; off > 0; off >>= 1) {
                g0 += __shfl_xor_sync(0xffffffffu, g0, off);
                g1 += __shfl_xor_sync(0xffffffffu, g1, off);
            }
            ACC_UPDATE(g0, v0_lo, v0_hi);
            ACC_UPDATE(g1, v1_lo, v1_hi);
        }
        if (i < pe) {
            const float4* r0 = (const float4*)(feat + (size_t)i * DD);
            const float4 v0_lo = __ldcs(&r0[lane]);
            const float4 v0_hi = __ldcs(&r0[lane + 32]);
            float g0 = dot8(v0_lo, v0_hi, w_lo, w_hi);
            #pragma unroll
            for (int off = 16; off > 0; off >>= 1)
                g0 += __shfl_xor_sync(0xffffffffu, g0, off);
            ACC_UPDATE(g0, v0_lo, v0_hi);
        }

        // ---- flush piece ----
        const bool whole  = (cur == a) && (pe == b);
        const bool starts = (cur > a) || (prevA != s);   // piece begins segment
        const bool ends   = (pe < b) || (nextB != s);    // piece ends segment

        float* dm; float* ds; float* da;
        if (whole) {
            dm = &g_cp_m[w]; ds = &g_cp_s[w]; da = &g_cp_acc[(size_t)w * DD];
        } else {
            const int idx = s * 2 + (starts ? 0 : 1);
            dm = &g_sp_m[idx]; ds = &g_sp_s[idx]; da = &g_sp_acc[(size_t)idx * DD];
        }
        if (lane == 0) {
            *dm = m; *ds = ssum;
            if (starts) g_ss[s] = cur;
            if (ends)   g_es[s] = pe;
        }
        ((float4*)da)[lane]      = acc_lo;
        ((float4*)da)[lane + 32] = acc_hi;

        cur = pe;
    }
}

// Piece j of segment s (pieces indexed w0..w1): resolve scratch location.
__device__ __forceinline__ void piece_ptrs(int s, int w, int ss, int es, int n, int C,
                                           const float** pm, const float** ps,
                                           const float** pa) {
    const bool whole = (ss <= w * C) && (es >= min(w * C + C, n));
    if (whole) {
        *pm = &g_cp_m[w]; *ps = &g_cp_s[w]; *pa = &g_cp_acc[(size_t)w * DD];
    } else {
        const int idx = s * 2 + ((w * C < ss || ss <= w * C) && (w == ss / C) ? 0 : 1);
        *pm = &g_sp_m[idx]; *ps = &g_sp_s[idx]; *pa = &g_sp_acc[(size_t)idx * DD];
    }
}

// one CTA (128 thr) per segment: two-pass merge (max, then independent
// scaled accumulation), normalize, write out.
__global__ __launch_bounds__(128) void pool_phase2(
    float* __restrict__ out, int n, int C)
{
    const int s   = blockIdx.x;
    const int tid = threadIdx.x;

    const int ss = g_ss[s];
    const int es = g_es[s];

    if (es <= ss) {   // empty segment (never written -> 0,0)
        out[(size_t)s * DD + tid]       = 0.0f;
        out[(size_t)s * DD + tid + 128] = 0.0f;
        return;
    }

    const int w0 = ss / C;
    const int w1 = (es - 1) / C;
    const int np = w1 - w0 + 1;

    __shared__ float sh_red[4];

    // ---- pass A: global max over piece maxima (independent strided loads) ----
    float lm = -INFINITY;
    for (int j = tid; j < np; j += 128) {
        const int w = w0 + j;
        const float* pm; const float* ps; const float* pa;
        piece_ptrs(s, w, ss, es, n, C, &pm, &ps, &pa);
        lm = fmaxf(lm, __ldg(pm));
    }
    #pragma unroll
    for (int off = 16; off > 0; off >>= 1)
        lm = fmaxf(lm, __shfl_xor_sync(0xffffffffu, lm, off));
    if ((tid & 31) == 0) sh_red[tid >> 5] = lm;
    __syncthreads();
    float M = fmaxf(fmaxf(sh_red[0], sh_red[1]), fmaxf(sh_red[2], sh_red[3]));

    // ---- pass B: independent scaled accumulation over all pieces ----
    float T = 0.0f, o0 = 0.0f, o1 = 0.0f;
    for (int j = 0; j < np; ++j) {
        const int w = w0 + j;
        const float* pm; const float* ps; const float* pa;
        piece_ptrs(s, w, ss, es, n, C, &pm, &ps, &pa);
        const float mj = __ldg(pm);           // uniform/broadcast
        const float sj = __ldg(ps);
        const float a0 = __ldg(&pa[tid]);
        const float a1 = __ldg(&pa[tid + 128]);
        const float sc = __expf(mj - M);
        T  = fmaf(sj, sc, T);
        o0 = fmaf(a0, sc, o0);
        o1 = fmaf(a1, sc, o1);
    }

    const float inv = 1.0f / T;
    out[(size_t)s * DD + tid]       = o0 * inv;
    out[(size_t)s * DD + tid + 128] = o1 * inv;
}

extern "C" void kernel_launch(void* const* d_in, const int* in_sizes, int n_in,
                              void* d_out, int out_size) {
    const float* feat  = (const float*)d_in[0];
    const float* Wg    = (const float*)d_in[1];
    const int*   seg32 = (const int*)d_in[3];   // int32 view; dtype detected on device

    const int n = in_sizes[0] / DD;
    int nseg = out_size / DD;
    if (nseg > MAXB) nseg = MAXB;

    const int C = (n + NWC - 1) / NWC;          // nodes per warp-chunk

    pool_phase1<<<G1, 128>>>(feat, Wg, seg32, n, C);
    pool_phase2<<<nseg, 128>>>((float*)d_out, n, C);
}